// round 1
// baseline (speedup 1.0000x reference)
#include <cuda_runtime.h>

#define NN 50000
#define NE 800000
#define RREL 8
#define DEMB 256
#define DHID 256
#define DOUT 128
#define DTXT 256

// ---------------- static device scratch (no allocation allowed) ----------------
__device__ int   g_cnt[NN * RREL];
__device__ float g_inv[NN * RREL];
__device__ float g_xW[(size_t)NN * RREL * DHID];   // 409.6 MB, reused by layer 2
__device__ float g_rootx[NN * DHID];               // reused by layer 2
__device__ float g_agg[NN * DHID];                 // reused by layer 2
__device__ float g_h1[NN * DHID];
__device__ float g_Hs[NN * DHID];
__device__ float g_Hd[NN * DHID];

// ---------------- tiny utility kernels ----------------
__global__ void zero4_kernel(float4* p, int n4) {
    int i = blockIdx.x * blockDim.x + threadIdx.x;
    if (i < n4) p[i] = make_float4(0.f, 0.f, 0.f, 0.f);
}
__global__ void zeroi_kernel(int* p, int n) {
    int i = blockIdx.x * blockDim.x + threadIdx.x;
    if (i < n) p[i] = 0;
}
__global__ void count_kernel(const int* __restrict__ dstv, const int* __restrict__ etype) {
    int e = blockIdx.x * blockDim.x + threadIdx.x;
    if (e < NE) atomicAdd(&g_cnt[dstv[e] * RREL + etype[e]], 1);
}
__global__ void inv_kernel() {
    int i = blockIdx.x * blockDim.x + threadIdx.x;
    if (i < NN * RREL) {
        int c = g_cnt[i];
        g_inv[i] = c > 0 ? 1.0f / (float)c : 0.0f;
    }
}

// out = relu(agg + rootx + bias), vectorized float4.  n4 = N*D/4, d4 = D/4
__global__ void add_relu_kernel(const float4* __restrict__ agg, const float4* __restrict__ rootx,
                                const float4* __restrict__ bias, float4* __restrict__ out,
                                int n4, int d4) {
    int i = blockIdx.x * blockDim.x + threadIdx.x;
    if (i >= n4) return;
    float4 a = agg[i], r = rootx[i], b = bias[i % d4];
    float4 o;
    o.x = fmaxf(a.x + r.x + b.x, 0.f);
    o.y = fmaxf(a.y + r.y + b.y, 0.f);
    o.z = fmaxf(a.z + r.z + b.z, 0.f);
    o.w = fmaxf(a.w + r.w + b.w, 0.f);
    out[i] = o;
}

// ---------------- scatter: agg[dst] += xW[src, rel] * inv[dst, rel] ----------------
template <int D>
__global__ void __launch_bounds__(256) scatter_kernel(const int* __restrict__ srcv,
                                                      const int* __restrict__ dstv,
                                                      const int* __restrict__ etype,
                                                      const float* __restrict__ inv,
                                                      const float* __restrict__ xW,
                                                      float* __restrict__ agg) {
    constexpr int V4 = D / 4;            // float4 chunks per row
    constexpr int EPB = 256 / V4;        // edges per block
    int e = blockIdx.x * EPB + threadIdx.x / V4;
    int c = threadIdx.x % V4;
    if (e >= NE) return;
    int s = srcv[e], d = dstv[e], r = etype[e];
    float w = inv[d * RREL + r];
    float4 v = *((const float4*)(xW + ((size_t)s * RREL + r) * D) + c);
    v.x *= w; v.y *= w; v.z *= w; v.w *= w;
    atomicAdd(((float4*)(agg + (size_t)d * D)) + c, v);
}

// ---------------- generic tiled SIMT GEMM: C = A[M,K] @ B[K,N] ----------------
// A row-major lda=K.  B row-major with ldb.  blockIdx.z strides B and C.
#define GBM 128
#define GBN 128
#define GBK 16
__global__ void __launch_bounds__(256) gemm_kernel(const float* __restrict__ A,
                                                   const float* __restrict__ B,
                                                   float* __restrict__ C,
                                                   int M, int N, int K, int ldb, int ldc,
                                                   long sB, long sC) {
    B += (long)blockIdx.z * sB;
    C += (long)blockIdx.z * sC;
    int bm = blockIdx.x * GBM;
    int bn = blockIdx.y * GBN;

    __shared__ float As[GBK][GBM];
    __shared__ float Bs[GBK][GBN];

    int tid = threadIdx.x;
    int tx = tid & 15, ty = tid >> 4;
    int arow = tid >> 1, acol = (tid & 1) * 8;
    int brow = tid >> 4, bcol = (tid & 15) * 8;

    float acc[8][8];
#pragma unroll
    for (int i = 0; i < 8; i++)
#pragma unroll
        for (int j = 0; j < 8; j++) acc[i][j] = 0.f;

    for (int kt = 0; kt < K; kt += GBK) {
        float4 a0, a1;
        if (bm + arow < M) {
            const float* ap = A + (size_t)(bm + arow) * K + kt + acol;
            a0 = *(const float4*)ap;
            a1 = *(const float4*)(ap + 4);
        } else {
            a0 = make_float4(0.f, 0.f, 0.f, 0.f);
            a1 = a0;
        }
        As[acol + 0][arow] = a0.x; As[acol + 1][arow] = a0.y;
        As[acol + 2][arow] = a0.z; As[acol + 3][arow] = a0.w;
        As[acol + 4][arow] = a1.x; As[acol + 5][arow] = a1.y;
        As[acol + 6][arow] = a1.z; As[acol + 7][arow] = a1.w;

        const float* bp = B + (size_t)(kt + brow) * ldb + bn + bcol;
        *(float4*)&Bs[brow][bcol]     = *(const float4*)bp;
        *(float4*)&Bs[brow][bcol + 4] = *(const float4*)(bp + 4);
        __syncthreads();

#pragma unroll
        for (int k = 0; k < GBK; k++) {
            float4 arl = *(float4*)&As[k][ty * 4];
            float4 arh = *(float4*)&As[k][64 + ty * 4];
            float4 brl = *(float4*)&Bs[k][tx * 4];
            float4 brh = *(float4*)&Bs[k][64 + tx * 4];
            float ar[8] = {arl.x, arl.y, arl.z, arl.w, arh.x, arh.y, arh.z, arh.w};
            float br[8] = {brl.x, brl.y, brl.z, brl.w, brh.x, brh.y, brh.z, brh.w};
#pragma unroll
            for (int i = 0; i < 8; i++)
#pragma unroll
                for (int j = 0; j < 8; j++) acc[i][j] = fmaf(ar[i], br[j], acc[i][j]);
        }
        __syncthreads();
    }

#pragma unroll
    for (int i = 0; i < 8; i++) {
        int r = (i < 4) ? (ty * 4 + i) : (64 + ty * 4 + (i - 4));
        if (bm + r < M) {
            float* cp = C + (size_t)(bm + r) * ldc + bn;
            *(float4*)(cp + tx * 4)      = make_float4(acc[i][0], acc[i][1], acc[i][2], acc[i][3]);
            *(float4*)(cp + 64 + tx * 4) = make_float4(acc[i][4], acc[i][5], acc[i][6], acc[i][7]);
        }
    }
}

// ---------------- fused edge MLP ----------------
// logits[e] = relu( e_text[e] @ Wt + Hs[src[e]] + Hd[dst[e]] + b1 ) . w2 + b2
// Tiled: 32 edges x 256 hidden, K = 256.
__global__ void __launch_bounds__(256) edge_mlp_kernel(const int* __restrict__ srcv,
                                                       const int* __restrict__ dstv,
                                                       const float* __restrict__ etext,
                                                       const float* __restrict__ Wt,   // mlpW1 + 256*256
                                                       const float* __restrict__ b1v,  // mlpb1 [256]
                                                       const float* __restrict__ w2v,  // mlpW2 [256]
                                                       const float* __restrict__ b2v,  // mlpb2 [1]
                                                       const float* __restrict__ Hs,
                                                       const float* __restrict__ Hd,
                                                       float* __restrict__ logits) {
    __shared__ float As[32][32];    // e_text tile, transposed [k][edge]
    __shared__ float Bs[32][256];   // Wt tile [k][hid]

    int tid = threadIdx.x;
    int tx = tid & 31;       // hidden-col group (0..31)
    int ty = tid >> 5;       // edge-row group (0..7); one warp per ty
    long ebase = (long)blockIdx.x * 32;

    int lr = tid >> 3;            // A load: row 0..31
    int lk = (tid & 7) * 4;       // A load: k offset
    int bk = tid >> 3;            // B load: k row 0..31
    int bf = tid & 7;             // B load: float4 lane

    float acc[4][8];
#pragma unroll
    for (int i = 0; i < 4; i++)
#pragma unroll
        for (int j = 0; j < 8; j++) acc[i][j] = 0.f;

    for (int kt = 0; kt < DTXT; kt += 32) {
        long er = ebase + lr;
        float4 av = (er < NE) ? *(const float4*)(etext + er * DTXT + kt + lk)
                              : make_float4(0.f, 0.f, 0.f, 0.f);
        As[lk + 0][lr] = av.x; As[lk + 1][lr] = av.y;
        As[lk + 2][lr] = av.z; As[lk + 3][lr] = av.w;

        const float* brp = Wt + (size_t)(kt + bk) * 256;
#pragma unroll
        for (int i = 0; i < 8; i++) {
            int f = bf + i * 8;
            *(float4*)&Bs[bk][f * 4] = *(const float4*)(brp + f * 4);
        }
        __syncthreads();

#pragma unroll
        for (int k = 0; k < 32; k++) {
            float a0 = As[k][ty * 4 + 0];
            float a1 = As[k][ty * 4 + 1];
            float a2 = As[k][ty * 4 + 2];
            float a3 = As[k][ty * 4 + 3];
            float4 bl = *(float4*)&Bs[k][tx * 4];
            float4 bh = *(float4*)&Bs[k][128 + tx * 4];
            float bv[8] = {bl.x, bl.y, bl.z, bl.w, bh.x, bh.y, bh.z, bh.w};
            float av4[4] = {a0, a1, a2, a3};
#pragma unroll
            for (int i = 0; i < 4; i++)
#pragma unroll
                for (int j = 0; j < 8; j++) acc[i][j] = fmaf(av4[i], bv[j], acc[i][j]);
        }
        __syncthreads();
    }

    // epilogue
    int c0 = tx * 4, c1 = 128 + tx * 4;
    float4 w2l = *(const float4*)(w2v + c0);
    float4 w2h = *(const float4*)(w2v + c1);
    float4 b1l = *(const float4*)(b1v + c0);
    float4 b1h = *(const float4*)(b1v + c1);
    float beta = b2v[0];
    float w2a[8] = {w2l.x, w2l.y, w2l.z, w2l.w, w2h.x, w2h.y, w2h.z, w2h.w};
    float b1a[8] = {b1l.x, b1l.y, b1l.z, b1l.w, b1h.x, b1h.y, b1h.z, b1h.w};

#pragma unroll
    for (int i = 0; i < 4; i++) {
        long e = ebase + ty * 4 + i;
        if (e < NE) {   // uniform across the warp (ty fixed per warp)
            int s = srcv[e], d = dstv[e];
            float4 hs0 = *(const float4*)(Hs + (size_t)s * 256 + c0);
            float4 hs1 = *(const float4*)(Hs + (size_t)s * 256 + c1);
            float4 hd0 = *(const float4*)(Hd + (size_t)d * 256 + c0);
            float4 hd1 = *(const float4*)(Hd + (size_t)d * 256 + c1);
            float hsa[8] = {hs0.x, hs0.y, hs0.z, hs0.w, hs1.x, hs1.y, hs1.z, hs1.w};
            float hda[8] = {hd0.x, hd0.y, hd0.z, hd0.w, hd1.x, hd1.y, hd1.z, hd1.w};
            float p = 0.f;
#pragma unroll
            for (int j = 0; j < 8; j++) {
                float h = acc[i][j] + hsa[j] + hda[j] + b1a[j];
                h = fmaxf(h, 0.f);
                p = fmaf(h, w2a[j], p);
            }
#pragma unroll
            for (int off = 16; off > 0; off >>= 1)
                p += __shfl_down_sync(0xffffffffu, p, off);
            if (tx == 0) logits[e] = p + beta;
        }
    }
}

// ---------------- launch ----------------
extern "C" void kernel_launch(void* const* d_in, const int* in_sizes, int n_in,
                              void* d_out, int out_size) {
    const int*   edge_index = (const int*)d_in[0];
    const int*   etype      = (const int*)d_in[1];
    const float* etext      = (const float*)d_in[2];
    const float* node_emb   = (const float*)d_in[3];
    const float* W1         = (const float*)d_in[4];
    const float* root1      = (const float*)d_in[5];
    const float* b1         = (const float*)d_in[6];
    const float* W2         = (const float*)d_in[7];
    const float* root2      = (const float*)d_in[8];
    const float* b2         = (const float*)d_in[9];
    const float* mlpW1      = (const float*)d_in[10];
    const float* mlpb1      = (const float*)d_in[11];
    const float* mlpW2      = (const float*)d_in[12];
    const float* mlpb2      = (const float*)d_in[13];

    const int* srcv = edge_index;
    const int* dstv = edge_index + NE;
    float* logits = (float*)d_out;
    float* h2     = (float*)d_out + NE;   // h output [N, 128]

    void *p;
    cudaGetSymbolAddress(&p, g_cnt);   int*   cnt   = (int*)p;
    cudaGetSymbolAddress(&p, g_inv);   float* inv   = (float*)p;
    cudaGetSymbolAddress(&p, g_xW);    float* xW    = (float*)p;
    cudaGetSymbolAddress(&p, g_rootx); float* rootx = (float*)p;
    cudaGetSymbolAddress(&p, g_agg);   float* agg   = (float*)p;
    cudaGetSymbolAddress(&p, g_h1);    float* h1    = (float*)p;
    cudaGetSymbolAddress(&p, g_Hs);    float* Hs    = (float*)p;
    cudaGetSymbolAddress(&p, g_Hd);    float* Hd    = (float*)p;

    const int MB = (NN + GBM - 1) / GBM;   // 391

    // counts + inverse
    zeroi_kernel<<<(NN * RREL + 255) / 256, 256>>>(cnt, NN * RREL);
    count_kernel<<<(NE + 255) / 256, 256>>>(dstv, etype);
    inv_kernel<<<(NN * RREL + 255) / 256, 256>>>();

    // ----- layer 1 -----
    // xW[n, r*256+j] = node_emb @ W1[r]
    gemm_kernel<<<dim3(MB, 2, 8), 256>>>(node_emb, W1, xW, NN, 256, 256,
                                         256, RREL * 256, 256L * 256, 256L);
    // rootx = node_emb @ root1
    gemm_kernel<<<dim3(MB, 2, 1), 256>>>(node_emb, root1, rootx, NN, 256, 256,
                                         256, 256, 0, 0);
    zero4_kernel<<<(NN * 256 / 4 + 255) / 256, 256>>>((float4*)agg, NN * 256 / 4);
    scatter_kernel<256><<<NE / 4, 256>>>(srcv, dstv, etype, inv, xW, agg);
    add_relu_kernel<<<(NN * 256 / 4 + 255) / 256, 256>>>(
        (const float4*)agg, (const float4*)rootx, (const float4*)b1,
        (float4*)h1, NN * 256 / 4, 64);

    // ----- layer 2 -----
    gemm_kernel<<<dim3(MB, 1, 8), 256>>>(h1, W2, xW, NN, 128, 256,
                                         128, RREL * 128, 256L * 128, 128L);
    gemm_kernel<<<dim3(MB, 1, 1), 256>>>(h1, root2, rootx, NN, 128, 256,
                                         128, 128, 0, 0);
    zero4_kernel<<<(NN * 128 / 4 + 255) / 256, 256>>>((float4*)agg, NN * 128 / 4);
    scatter_kernel<128><<<NE / 8, 256>>>(srcv, dstv, etype, inv, xW, agg);
    add_relu_kernel<<<(NN * 128 / 4 + 255) / 256, 256>>>(
        (const float4*)agg, (const float4*)rootx, (const float4*)b2,
        (float4*)h2, NN * 128 / 4, 32);

    // ----- edge MLP -----
    // Hs = h2 @ mlpW1[0:128], Hd = h2 @ mlpW1[128:256]
    gemm_kernel<<<dim3(MB, 2, 1), 256>>>(h2, mlpW1, Hs, NN, 256, 128,
                                         256, 256, 0, 0);
    gemm_kernel<<<dim3(MB, 2, 1), 256>>>(h2, mlpW1 + 128 * 256, Hd, NN, 256, 128,
                                         256, 256, 0, 0);
    edge_mlp_kernel<<<NE / 32, 256>>>(srcv, dstv, etext, mlpW1 + 256 * 256,
                                      mlpb1, mlpW2, mlpb2, Hs, Hd, logits);
}

// round 3
// speedup vs baseline: 1.1114x; 1.1114x over previous
#include <cuda_runtime.h>
#include <mma.h>
#include <cstdint>

using namespace nvcuda;

#define NN 50000
#define NP 50048        // padded rows: 391 * 128
#define NE 800000
#define RREL 8

// ---------------- static device scratch ----------------
__device__ int   g_cnt[NN * RREL];
__device__ float g_inv[NN * RREL];
__device__ float g_xW[(size_t)NP * 2048];    // 410 MB, layer-1 xW; layer-2 reuses
__device__ float g_rootx[NP * 256];
__device__ float g_agg[NN * 256];
__device__ float g_h1[NN * 256];
__device__ float g_Hs[NP * 256];
__device__ float g_Hd[NP * 256];

__device__ __forceinline__ float to_tf32(float x) {
    float y;
    asm("cvt.rna.tf32.f32 %0, %1;" : "=f"(y) : "f"(x));
    return y;
}

// ================= wmma tf32 GEMM =================
// C[M, 128*gridDim.y] = A[M,K] @ B[K,N]   (B row-major [k][n], ld = ldb)
// Block tile 128x128, 8 warps (2M x 4N), warp tile 64x32, K-step 16.
#define ALD 24     // A smem ld (floats)
#define BLD 132    // B smem ld (floats)
__global__ void __launch_bounds__(256) twmma_kernel(const float* __restrict__ A,
                                                    const float* __restrict__ B,
                                                    float* __restrict__ C,
                                                    int M, int K, int ldb, int ldc,
                                                    long sB, long sC) {
    __shared__ float sA[128 * ALD];
    __shared__ float sB_[16 * BLD];

    B += (long)blockIdx.z * sB;
    C += (long)blockIdx.z * sC;
    int bm = blockIdx.x * 128;
    int bn = blockIdx.y * 128;

    int tid = threadIdx.x;
    int w = tid >> 5;
    int wm = w & 1;          // 0..1  (64-row half)
    int wn = w >> 1;         // 0..3  (32-col quarter)

    wmma::fragment<wmma::accumulator, 16, 16, 8, float> acc[4][2];
#pragma unroll
    for (int i = 0; i < 4; i++)
#pragma unroll
        for (int j = 0; j < 2; j++) wmma::fill_fragment(acc[i][j], 0.f);

    // load mappings
    int ar = tid >> 1, ah = (tid & 1) * 8;        // A: row, 8-float half
    int br = tid >> 4, bc = (tid & 15) * 8;       // B: k-row, col group

    for (int kt = 0; kt < K; kt += 16) {
        // stage A 128x16 (guard rows), convert to tf32
        {
            bool ok = (bm + ar) < M;
            const float4* ap = (const float4*)(A + (size_t)(bm + ar) * K + kt + ah);
            float4 v0 = ok ? __ldg(ap)     : make_float4(0.f, 0.f, 0.f, 0.f);
            float4 v1 = ok ? __ldg(ap + 1) : make_float4(0.f, 0.f, 0.f, 0.f);
            float* s = sA + ar * ALD + ah;
            s[0] = to_tf32(v0.x); s[1] = to_tf32(v0.y); s[2] = to_tf32(v0.z); s[3] = to_tf32(v0.w);
            s[4] = to_tf32(v1.x); s[5] = to_tf32(v1.y); s[6] = to_tf32(v1.z); s[7] = to_tf32(v1.w);
        }
        // stage B 16x128
        {
            const float4* bp = (const float4*)(B + (size_t)(kt + br) * ldb + bn + bc);
            float4 v0 = __ldg(bp), v1 = __ldg(bp + 1);
            float* s = sB_ + br * BLD + bc;
            s[0] = to_tf32(v0.x); s[1] = to_tf32(v0.y); s[2] = to_tf32(v0.z); s[3] = to_tf32(v0.w);
            s[4] = to_tf32(v1.x); s[5] = to_tf32(v1.y); s[6] = to_tf32(v1.z); s[7] = to_tf32(v1.w);
        }
        __syncthreads();

#pragma unroll
        for (int ks = 0; ks < 16; ks += 8) {
            wmma::fragment<wmma::matrix_a, 16, 16, 8, wmma::precision::tf32, wmma::row_major> af[4];
            wmma::fragment<wmma::matrix_b, 16, 16, 8, wmma::precision::tf32, wmma::row_major> bf[2];
#pragma unroll
            for (int i = 0; i < 4; i++)
                wmma::load_matrix_sync(af[i], sA + (wm * 64 + i * 16) * ALD + ks, ALD);
#pragma unroll
            for (int j = 0; j < 2; j++)
                wmma::load_matrix_sync(bf[j], sB_ + ks * BLD + wn * 32 + j * 16, BLD);
#pragma unroll
            for (int i = 0; i < 4; i++)
#pragma unroll
                for (int j = 0; j < 2; j++)
                    wmma::mma_sync(acc[i][j], af[i], bf[j], acc[i][j]);
        }
        __syncthreads();
    }

    // store (C rows padded to multiples of 128 — no guard needed)
#pragma unroll
    for (int i = 0; i < 4; i++)
#pragma unroll
        for (int j = 0; j < 2; j++) {
            size_t off = (size_t)(bm + wm * 64 + i * 16) * ldc + bn + wn * 32 + j * 16;
            wmma::store_matrix_sync(C + off, acc[i][j], ldc, wmma::mem_row_major);
        }
}

// ================= fused edge MLP =================
// 64 edges x 256 hidden per block; text GEMM by wmma, epilogue gathers Hs/Hd,
// adds bias, relu, dots with w2, warp-reduces per edge.
#define EALD 24
#define EBLD 260
__global__ void __launch_bounds__(256) edge_fused_kernel(const int* __restrict__ srcv,
                                                         const int* __restrict__ dstv,
                                                         const float* __restrict__ etext,
                                                         const float* __restrict__ Wt,   // [256][256]
                                                         const float* __restrict__ b1v,
                                                         const float* __restrict__ w2v,
                                                         const float* __restrict__ b2v,
                                                         const float* __restrict__ Hs,
                                                         const float* __restrict__ Hd,
                                                         float* __restrict__ logits) {
    extern __shared__ float smem[];
    float* sA = smem;                      // [64][EALD]   6144 B
    float* sB = smem + 64 * EALD;          // [16][EBLD]  16640 B
    float* sC = smem;                      // [64][256]   65536 B (overlaid after GEMM)

    int tid = threadIdx.x;
    int w = tid >> 5, lane = tid & 31;
    int bm = blockIdx.x * 64;

    wmma::fragment<wmma::accumulator, 16, 16, 8, float> acc[4][2];
#pragma unroll
    for (int i = 0; i < 4; i++)
#pragma unroll
        for (int j = 0; j < 2; j++) wmma::fill_fragment(acc[i][j], 0.f);

    int ar = tid >> 2, aq = (tid & 3) * 4;        // A: 64 rows x 16 (4 floats/thread)
    int br = tid >> 4, bc = (tid & 15) * 16;      // B: 16 rows x 256 (16 floats/thread)

    for (int kt = 0; kt < 256; kt += 16) {
        {
            float4 v = __ldg((const float4*)(etext + (size_t)(bm + ar) * 256 + kt + aq));
            float* s = sA + ar * EALD + aq;
            s[0] = to_tf32(v.x); s[1] = to_tf32(v.y); s[2] = to_tf32(v.z); s[3] = to_tf32(v.w);
        }
        {
            const float4* bp = (const float4*)(Wt + (size_t)(kt + br) * 256 + bc);
            float* s = sB + br * EBLD + bc;
#pragma unroll
            for (int q = 0; q < 4; q++) {
                float4 v = __ldg(bp + q);
                s[q * 4 + 0] = to_tf32(v.x); s[q * 4 + 1] = to_tf32(v.y);
                s[q * 4 + 2] = to_tf32(v.z); s[q * 4 + 3] = to_tf32(v.w);
            }
        }
        __syncthreads();

#pragma unroll
        for (int ks = 0; ks < 16; ks += 8) {
            wmma::fragment<wmma::matrix_a, 16, 16, 8, wmma::precision::tf32, wmma::row_major> af[4];
            wmma::fragment<wmma::matrix_b, 16, 16, 8, wmma::precision::tf32, wmma::row_major> bf[2];
#pragma unroll
            for (int i = 0; i < 4; i++)
                wmma::load_matrix_sync(af[i], sA + (i * 16) * EALD + ks, EALD);
#pragma unroll
            for (int j = 0; j < 2; j++)
                wmma::load_matrix_sync(bf[j], sB + ks * EBLD + w * 32 + j * 16, EBLD);
#pragma unroll
            for (int i = 0; i < 4; i++)
#pragma unroll
                for (int j = 0; j < 2; j++)
                    wmma::mma_sync(acc[i][j], af[i], bf[j], acc[i][j]);
        }
        __syncthreads();
    }

    // dump C tile to SMEM (overlays sA/sB — already synced)
#pragma unroll
    for (int i = 0; i < 4; i++)
#pragma unroll
        for (int j = 0; j < 2; j++)
            wmma::store_matrix_sync(sC + (i * 16) * 256 + w * 32 + j * 16, acc[i][j],
                                    256, wmma::mem_row_major);
    __syncthreads();

    // epilogue: warp w handles edges w*8 .. w*8+7; lane covers 8 cols
    int c0 = lane * 8;
    float4 b1a = __ldg((const float4*)(b1v + c0));
    float4 b1b = __ldg((const float4*)(b1v + c0 + 4));
    float4 w2a = __ldg((const float4*)(w2v + c0));
    float4 w2b = __ldg((const float4*)(w2v + c0 + 4));
    float beta = __ldg(b2v);

#pragma unroll
    for (int ei = 0; ei < 8; ei++) {
        int el = w * 8 + ei;
        int e = bm + el;
        int s = __ldg(srcv + e), d = __ldg(dstv + e);
        float4 ca = *(float4*)(sC + el * 256 + c0);
        float4 cb = *(float4*)(sC + el * 256 + c0 + 4);
        float4 hsa = __ldg((const float4*)(Hs + (size_t)s * 256 + c0));
        float4 hsb = __ldg((const float4*)(Hs + (size_t)s * 256 + c0 + 4));
        float4 hda = __ldg((const float4*)(Hd + (size_t)d * 256 + c0));
        float4 hdb = __ldg((const float4*)(Hd + (size_t)d * 256 + c0 + 4));
        float p = 0.f, h;
        h = fmaxf(ca.x + hsa.x + hda.x + b1a.x, 0.f); p = fmaf(h, w2a.x, p);
        h = fmaxf(ca.y + hsa.y + hda.y + b1a.y, 0.f); p = fmaf(h, w2a.y, p);
        h = fmaxf(ca.z + hsa.z + hda.z + b1a.z, 0.f); p = fmaf(h, w2a.z, p);
        h = fmaxf(ca.w + hsa.w + hda.w + b1a.w, 0.f); p = fmaf(h, w2a.w, p);
        h = fmaxf(cb.x + hsb.x + hdb.x + b1b.x, 0.f); p = fmaf(h, w2b.x, p);
        h = fmaxf(cb.y + hsb.y + hdb.y + b1b.y, 0.f); p = fmaf(h, w2b.y, p);
        h = fmaxf(cb.z + hsb.z + hdb.z + b1b.z, 0.f); p = fmaf(h, w2b.z, p);
        h = fmaxf(cb.w + hsb.w + hdb.w + b1b.w, 0.f); p = fmaf(h, w2b.w, p);
#pragma unroll
        for (int off = 16; off > 0; off >>= 1)
            p += __shfl_down_sync(0xffffffffu, p, off);
        if (lane == 0) logits[e] = p + beta;
    }
}

// ================= elementwise / scatter =================
__global__ void zero4_kernel(float4* p, int n4) {
    int i = blockIdx.x * blockDim.x + threadIdx.x;
    if (i < n4) p[i] = make_float4(0.f, 0.f, 0.f, 0.f);
}
__global__ void zeroi_kernel(int* p, int n) {
    int i = blockIdx.x * blockDim.x + threadIdx.x;
    if (i < n) p[i] = 0;
}
__global__ void count_kernel(const int* __restrict__ dstv, const int* __restrict__ etype) {
    int e = blockIdx.x * blockDim.x + threadIdx.x;
    if (e < NE) atomicAdd(&g_cnt[dstv[e] * RREL + etype[e]], 1);
}
__global__ void inv_kernel() {
    int i = blockIdx.x * blockDim.x + threadIdx.x;
    if (i < NN * RREL) {
        int c = g_cnt[i];
        g_inv[i] = c > 0 ? 1.0f / (float)c : 0.0f;
    }
}
__global__ void add_relu_kernel(const float4* __restrict__ agg, const float4* __restrict__ rootx,
                                const float4* __restrict__ bias, float4* __restrict__ out,
                                int n4, int d4) {
    int i = blockIdx.x * blockDim.x + threadIdx.x;
    if (i >= n4) return;
    float4 a = agg[i], r = rootx[i], b = bias[i % d4];
    float4 o;
    o.x = fmaxf(a.x + r.x + b.x, 0.f);
    o.y = fmaxf(a.y + r.y + b.y, 0.f);
    o.z = fmaxf(a.z + r.z + b.z, 0.f);
    o.w = fmaxf(a.w + r.w + b.w, 0.f);
    out[i] = o;
}
template <int D>
__global__ void __launch_bounds__(256) scatter_kernel(const int* __restrict__ srcv,
                                                      const int* __restrict__ dstv,
                                                      const int* __restrict__ etype,
                                                      const float* __restrict__ inv,
                                                      const float* __restrict__ xW,
                                                      float* __restrict__ agg) {
    constexpr int V4 = D / 4;
    constexpr int EPB = 256 / V4;
    int e = blockIdx.x * EPB + threadIdx.x / V4;
    int c = threadIdx.x % V4;
    if (e >= NE) return;
    int s = srcv[e], d = dstv[e], r = etype[e];
    float w = inv[d * RREL + r];
    float4 v = *((const float4*)(xW + ((size_t)s * RREL + r) * D) + c);
    v.x *= w; v.y *= w; v.z *= w; v.w *= w;
    atomicAdd(((float4*)(agg + (size_t)d * D)) + c, v);
}

// ================= launch =================
extern "C" void kernel_launch(void* const* d_in, const int* in_sizes, int n_in,
                              void* d_out, int out_size) {
    const int*   edge_index = (const int*)d_in[0];
    const int*   etype      = (const int*)d_in[1];
    const float* etext      = (const float*)d_in[2];
    const float* node_emb   = (const float*)d_in[3];
    const float* W1         = (const float*)d_in[4];
    const float* root1      = (const float*)d_in[5];
    const float* b1         = (const float*)d_in[6];
    const float* W2         = (const float*)d_in[7];
    const float* root2      = (const float*)d_in[8];
    const float* b2         = (const float*)d_in[9];
    const float* mlpW1      = (const float*)d_in[10];
    const float* mlpb1      = (const float*)d_in[11];
    const float* mlpW2      = (const float*)d_in[12];
    const float* mlpb2      = (const float*)d_in[13];

    const int* srcv = edge_index;
    const int* dstv = edge_index + NE;
    float* logits = (float*)d_out;
    float* h2     = (float*)d_out + NE;

    void* p;
    cudaGetSymbolAddress(&p, g_cnt);   int*   cntp  = (int*)p;
    cudaGetSymbolAddress(&p, g_inv);   float* inv   = (float*)p;
    cudaGetSymbolAddress(&p, g_xW);    float* xW    = (float*)p;
    cudaGetSymbolAddress(&p, g_rootx); float* rootx = (float*)p;
    cudaGetSymbolAddress(&p, g_agg);   float* agg   = (float*)p;
    cudaGetSymbolAddress(&p, g_h1);    float* h1    = (float*)p;
    cudaGetSymbolAddress(&p, g_Hs);    float* Hs    = (float*)p;
    cudaGetSymbolAddress(&p, g_Hd);    float* Hd    = (float*)p;

    const int EDGE_SMEM = 64 * 256 * 4;   // 65536
    cudaFuncSetAttribute(edge_fused_kernel, cudaFuncAttributeMaxDynamicSharedMemorySize, EDGE_SMEM);

    // counts / inv
    zeroi_kernel<<<(NN * RREL + 255) / 256, 256>>>(cntp, NN * RREL);
    count_kernel<<<(NE + 255) / 256, 256>>>(dstv, etype);
    inv_kernel<<<(NN * RREL + 255) / 256, 256>>>();

    const int MB = NP / 128;  // 391

    // ---- layer 1 ----
    // xW[n][r*256 + c] = node_emb @ W1[r]
    twmma_kernel<<<dim3(MB, 2, 8), 256>>>(node_emb, W1, xW, NN, 256, 256, 2048, 65536L, 256L);
    twmma_kernel<<<dim3(MB, 2, 1), 256>>>(node_emb, root1, rootx, NN, 256, 256, 256, 0L, 0L);
    zero4_kernel<<<(NN * 256 / 4 + 255) / 256, 256>>>((float4*)agg, NN * 256 / 4);
    scatter_kernel<256><<<NE / 4, 256>>>(srcv, dstv, etype, inv, xW, agg);
    add_relu_kernel<<<(NN * 256 / 4 + 255) / 256, 256>>>(
        (const float4*)agg, (const float4*)rootx, (const float4*)b1,
        (float4*)h1, NN * 256 / 4, 64);

    // ---- layer 2 ----
    // xW[n][r*128 + c] = h1 @ W2[r]
    twmma_kernel<<<dim3(MB, 1, 8), 256>>>(h1, W2, xW, NN, 256, 128, 1024, 32768L, 128L);
    twmma_kernel<<<dim3(MB, 1, 1), 256>>>(h1, root2, rootx, NN, 256, 128, 128, 0L, 0L);
    zero4_kernel<<<(NN * 128 / 4 + 255) / 256, 256>>>((float4*)agg, NN * 128 / 4);
    scatter_kernel<128><<<NE / 8, 256>>>(srcv, dstv, etype, inv, xW, agg);
    add_relu_kernel<<<(NN * 128 / 4 + 255) / 256, 256>>>(
        (const float4*)agg, (const float4*)rootx, (const float4*)b2,
        (float4*)h2, NN * 128 / 4, 32);

    // ---- edge MLP ----
    twmma_kernel<<<dim3(MB, 2, 1), 256>>>(h2, mlpW1, Hs, NN, 128, 256, 256, 0L, 0L);
    twmma_kernel<<<dim3(MB, 2, 1), 256>>>(h2, mlpW1 + 128 * 256, Hd, NN, 128, 256, 256, 0L, 0L);
    edge_fused_kernel<<<NE / 64, 256, EDGE_SMEM>>>(srcv, dstv, etext, mlpW1 + 256 * 256,
                                                   mlpb1, mlpW2, mlpb2, Hs, Hd, logits);
}